// round 9
// baseline (speedup 1.0000x reference)
#include <cuda_runtime.h>
#include <cstdint>

// ---------------------------------------------------------------------------
// voltageNN: 2-layer LSTM (H=256, proj P=1, in=1, T=1000) + MLP head, B=16384.
// TWO batch elements per warp (shared weights, independent recurrence chains
// to fill MUFU/SHFL latency bubbles). Activation split (per element):
//   i, f, g gates (24) + tanh(c) pair 0 (2)  -> MUFU tanh.approx.f32 (208 cyc)
//   o gate (4 pairs) + tanh(c) pairs 1-3     -> deg-13 odd Chebyshev on
//                                               [-1.8,1.8], packed fma.rn.f32x2
// Whh in SMEM (one read serves both elements). Runtime Chebyshev fit; exact
// MUFU fallback for |arg| > 1.75 (range analysis says never taken).
// ---------------------------------------------------------------------------

#define HID   256
#define TLEN  1000
#define FULLM 0xffffffffu
#define FIT_L    1.8
#define FALLBACK 1.75f
#define NPOLY 7            // deg-13 odd: coeffs of u^1..u^13

typedef unsigned long long u64;

// Packed f32-pair weights: [layer][pair 0..3][gate i,f,o,g][lane].
// lo = unit (lane + 64*pair), hi = unit (+32). i/f/o pre-scaled by 0.5
// (sigmoid(x) = 0.5*tanh(0.5x)+0.5).
__device__ float2 g_wx2[2][4][4][32];
__device__ float2 g_wh2[2][4][4][32];
__device__ float2 g_wb2[2][4][4][32];
__device__ float2 g_wr2[2][4][32];       // projection Whr pairs
__device__ float  g_poly[NPOLY];         // tanh odd-poly coeffs (deg 13)
__device__ float  g_w1t[TLEN * 128];     // W1 transposed + padded: [t][j]
__device__ float  g_b1p[128];
__device__ float  g_w2p[128];

// ---- f32x2 packed helpers (sm_100+) ----
__device__ __forceinline__ u64 pack2(float lo, float hi) {
    u64 r; asm("mov.b64 %0, {%1, %2};" : "=l"(r) : "f"(lo), "f"(hi)); return r;
}
__device__ __forceinline__ void unpack2(u64 v, float& lo, float& hi) {
    asm("mov.b64 {%0, %1}, %2;" : "=f"(lo), "=f"(hi) : "l"(v));
}
__device__ __forceinline__ u64 fma2(u64 a, u64 b, u64 c) {
    u64 r; asm("fma.rn.f32x2 %0, %1, %2, %3;" : "=l"(r) : "l"(a), "l"(b), "l"(c));
    return r;
}
__device__ __forceinline__ u64 mul2(u64 a, u64 b) {
    u64 r; asm("mul.rn.f32x2 %0, %1, %2;" : "=l"(r) : "l"(a), "l"(b)); return r;
}
__device__ __forceinline__ u64 ldp(const float2* p) {
    float2 v = *p; return pack2(v.x, v.y);
}
__device__ __forceinline__ float tanh_fast(float x) {
    float y; asm("tanh.approx.f32 %0, %1;" : "=f"(y) : "f"(x)); return y;
}
__device__ __forceinline__ uint32_t smem_u32(const void* p) {
    uint32_t a;
    asm("{ .reg .u64 t; cvta.to.shared.u64 t, %1; cvt.u32.u64 %0, t; }"
        : "=r"(a) : "l"(p));
    return a;
}
// volatile LDS.64: keeps loop-invariant weights out of the register budget.
__device__ __forceinline__ u64 lds64v(uint32_t addr) {
    u64 r; asm volatile("ld.shared.b64 %0, [%1];" : "=l"(r) : "r"(addr));
    return r;
}
// deg-13 odd polynomial tanh on packed pair (valid on |u| <= FIT_L).
__device__ __forceinline__ u64 tanh_poly2(u64 u2, const u64* B) {
    u64 s2 = mul2(u2, u2);
    u64 p = B[6];
    p = fma2(p, s2, B[5]);
    p = fma2(p, s2, B[4]);
    p = fma2(p, s2, B[3]);
    p = fma2(p, s2, B[2]);
    p = fma2(p, s2, B[1]);
    p = fma2(p, s2, B[0]);
    return mul2(p, u2);
}

// ---------------------------------------------------------------------------
// Prep kernel: pack/transpose weights + runtime Chebyshev fit of tanh.
// grid = TLEN+1 blocks x 128 threads.
// ---------------------------------------------------------------------------
__global__ void prep_kernel(
    const float* __restrict__ Wih0, const float* __restrict__ Whh0,
    const float* __restrict__ bih0, const float* __restrict__ bhh0,
    const float* __restrict__ Whr0,
    const float* __restrict__ Wih1, const float* __restrict__ Whh1,
    const float* __restrict__ bih1, const float* __restrict__ bhh1,
    const float* __restrict__ Whr1,
    const float* __restrict__ W1,  const float* __restrict__ b1,
    const float* __restrict__ W2)
{
    int tid = threadIdx.x;
    int blk = blockIdx.x;
    if (blk < TLEN) {
        int t = blk;
        int j = tid;  // 0..127
        g_w1t[t * 128 + j] = (j < 100) ? W1[j * TLEN + t] : 0.0f;
        return;
    }
    // ---- pack LSTM weights: 2 layers x 4 pairs x 32 lanes ----
    for (int i = tid; i < 256; i += 128) {
        int layer = i >> 7;
        int rem   = i & 127;
        int p     = rem >> 5;
        int lane  = rem & 31;
        int klo = lane + 64 * p;
        int khi = klo + 32;
        const float* Wih = layer ? Wih1 : Wih0;
        const float* Whh = layer ? Whh1 : Whh0;
        const float* bih = layer ? bih1 : bih0;
        const float* bhh = layer ? bhh1 : bhh0;
        const float* Whr = layer ? Whr1 : Whr0;
        // source gate stacking: i [0,256), f [256,512), g [512,768), o [768,1024)
        const int rows[4] = {0, 256, 768, 512};   // our order: i, f, o, g
        const float scl[4] = {0.5f, 0.5f, 0.5f, 1.0f};
#pragma unroll
        for (int gte = 0; gte < 4; gte++) {
            int r = rows[gte];
            float s = scl[gte];
            g_wx2[layer][p][gte][lane] = make_float2(s * Wih[r + klo], s * Wih[r + khi]);
            g_wh2[layer][p][gte][lane] = make_float2(s * Whh[r + klo], s * Whh[r + khi]);
            g_wb2[layer][p][gte][lane] = make_float2(s * (bih[r + klo] + bhh[r + klo]),
                                                     s * (bih[r + khi] + bhh[r + khi]));
        }
        g_wr2[layer][p][lane] = make_float2(Whr[klo], Whr[khi]);
    }
    if (tid < 128) {
        g_b1p[tid] = (tid < 100) ? b1[tid] : 0.0f;
        g_w2p[tid] = (tid < 100) ? W2[tid] : 0.0f;
    }
    // ---- Chebyshev fit of tanh on [-L, L], deg 13 odd, runtime in double ----
    if (tid == 0) {
        const double PI = 3.14159265358979323846;
        const double L = FIT_L;
        const int KMAX = 13, NN = 64;
        double c[KMAX + 1];
        for (int k = 0; k <= KMAX; k++) {
            double s = 0.0;
            for (int j = 0; j < NN; j++) {
                double th = PI * (j + 0.5) / NN;
                s += tanh(L * cos(th)) * cos(k * th);
            }
            c[k] = 2.0 / NN * s;
        }
        double T[KMAX + 1][KMAX + 1];
        for (int k = 0; k <= KMAX; k++)
            for (int i = 0; i <= KMAX; i++) T[k][i] = 0.0;
        T[0][0] = 1.0; T[1][1] = 1.0;
        for (int k = 2; k <= KMAX; k++)
            for (int i = 0; i <= KMAX; i++)
                T[k][i] = 2.0 * (i > 0 ? T[k - 1][i - 1] : 0.0) - T[k - 2][i];
        double mono[KMAX + 1];
        for (int i = 0; i <= KMAX; i++) mono[i] = 0.0;
        for (int k = 1; k <= KMAX; k += 2)          // odd terms only
            for (int i = 0; i <= KMAX; i++) mono[i] += c[k] * T[k][i];
        double Lp = L;
        for (int m = 0; m < NPOLY; m++) {           // coeff of u^(2m+1)
            g_poly[m] = (float)(mono[2 * m + 1] / Lp);
            Lp *= L * L;
        }
    }
}

// ---------------------------------------------------------------------------
// One dual-element LSTM step. Elements A and B share all weights (regs+SMEM);
// their dependency chains interleave to fill pipe bubbles.
// ---------------------------------------------------------------------------
__device__ __forceinline__ void lstm_step2(
    float xvA, float xvB, float& hA, float& hB,
    const u64 (*wx)[4], const u64 (*wb)[4], const u64* wr,
    float* cA, float* cB, const u64* B, uint32_t whaddr)
{
    const u64 halfc = pack2(0.5f, 0.5f);
    u64 xA2 = pack2(xvA, xvA), xB2 = pack2(xvB, xvB);
    u64 hA2 = pack2(hA, hA),   hB2 = pack2(hB, hB);
    u64 partA = 0ull, partB = 0ull;
    float runmax = 0.0f;
#pragma unroll
    for (int p = 0; p < 4; p++) {
        // Whh from shared — one load serves both elements
        u64 whi = lds64v(whaddr + (p * 4 + 0) * 256);
        u64 whf = lds64v(whaddr + (p * 4 + 1) * 256);
        u64 who = lds64v(whaddr + (p * 4 + 2) * 256);
        u64 whg = lds64v(whaddr + (p * 4 + 3) * 256);
        u64 aiA = fma2(xA2, wx[p][0], fma2(hA2, whi, wb[p][0]));
        u64 afA = fma2(xA2, wx[p][1], fma2(hA2, whf, wb[p][1]));
        u64 aoA = fma2(xA2, wx[p][2], fma2(hA2, who, wb[p][2]));
        u64 agA = fma2(xA2, wx[p][3], fma2(hA2, whg, wb[p][3]));
        u64 aiB = fma2(xB2, wx[p][0], fma2(hB2, whi, wb[p][0]));
        u64 afB = fma2(xB2, wx[p][1], fma2(hB2, whf, wb[p][1]));
        u64 aoB = fma2(xB2, wx[p][2], fma2(hB2, who, wb[p][2]));
        u64 agB = fma2(xB2, wx[p][3], fma2(hB2, whg, wb[p][3]));

        float v0, v1;
        // ---- element A: i,f,g on MUFU; cell; tanh(c); o poly ----
        unpack2(aiA, v0, v1);
        float giAl = fmaf(tanh_fast(v0), 0.5f, 0.5f);
        float giAh = fmaf(tanh_fast(v1), 0.5f, 0.5f);
        unpack2(afA, v0, v1);
        float gfAl = fmaf(tanh_fast(v0), 0.5f, 0.5f);
        float gfAh = fmaf(tanh_fast(v1), 0.5f, 0.5f);
        unpack2(agA, v0, v1);
        float ggAl = tanh_fast(v0);
        float ggAh = tanh_fast(v1);
        float cAl = fmaf(gfAl, cA[2 * p],     giAl * ggAl);
        float cAh = fmaf(gfAh, cA[2 * p + 1], giAh * ggAh);
        cA[2 * p] = cAl; cA[2 * p + 1] = cAh;
        u64 tcA;
        if (p == 0) {
            tcA = pack2(tanh_fast(cAl), tanh_fast(cAh));
        } else {
            tcA = tanh_poly2(pack2(cAl, cAh), B);
            runmax = fmaxf(runmax, fmaxf(fabsf(cAl), fabsf(cAh)));
        }
        u64 goA = fma2(tanh_poly2(aoA, B), halfc, halfc);
        unpack2(aoA, v0, v1);
        runmax = fmaxf(runmax, fmaxf(fabsf(v0), fabsf(v1)));
        partA = fma2(mul2(goA, tcA), wr[p], partA);

        // ---- element B ----
        unpack2(aiB, v0, v1);
        float giBl = fmaf(tanh_fast(v0), 0.5f, 0.5f);
        float giBh = fmaf(tanh_fast(v1), 0.5f, 0.5f);
        unpack2(afB, v0, v1);
        float gfBl = fmaf(tanh_fast(v0), 0.5f, 0.5f);
        float gfBh = fmaf(tanh_fast(v1), 0.5f, 0.5f);
        unpack2(agB, v0, v1);
        float ggBl = tanh_fast(v0);
        float ggBh = tanh_fast(v1);
        float cBl = fmaf(gfBl, cB[2 * p],     giBl * ggBl);
        float cBh = fmaf(gfBh, cB[2 * p + 1], giBh * ggBh);
        cB[2 * p] = cBl; cB[2 * p + 1] = cBh;
        u64 tcB;
        if (p == 0) {
            tcB = pack2(tanh_fast(cBl), tanh_fast(cBh));
        } else {
            tcB = tanh_poly2(pack2(cBl, cBh), B);
            runmax = fmaxf(runmax, fmaxf(fabsf(cBl), fabsf(cBh)));
        }
        u64 goB = fma2(tanh_poly2(aoB, B), halfc, halfc);
        unpack2(aoB, v0, v1);
        runmax = fmaxf(runmax, fmaxf(fabsf(v0), fabsf(v1)));
        partB = fma2(mul2(goB, tcB), wr[p], partB);
    }
    // never-taken (by range analysis) exact fallback: redo projection on MUFU
    if (__any_sync(FULLM, runmax > FALLBACK)) {
        partA = 0ull; partB = 0ull;
#pragma unroll
        for (int p = 0; p < 4; p++) {
            u64 who = lds64v(whaddr + (p * 4 + 2) * 256);
            u64 aoA = fma2(xA2, wx[p][2], fma2(hA2, who, wb[p][2]));
            u64 aoB = fma2(xB2, wx[p][2], fma2(hB2, who, wb[p][2]));
            float v0, v1;
            unpack2(aoA, v0, v1);
            u64 goA = pack2(fmaf(tanh_fast(v0), 0.5f, 0.5f),
                            fmaf(tanh_fast(v1), 0.5f, 0.5f));
            u64 tcA = pack2(tanh_fast(cA[2 * p]), tanh_fast(cA[2 * p + 1]));
            partA = fma2(mul2(goA, tcA), wr[p], partA);
            unpack2(aoB, v0, v1);
            u64 goB = pack2(fmaf(tanh_fast(v0), 0.5f, 0.5f),
                            fmaf(tanh_fast(v1), 0.5f, 0.5f));
            u64 tcB = pack2(tanh_fast(cB[2 * p]), tanh_fast(cB[2 * p + 1]));
            partB = fma2(mul2(goB, tcB), wr[p], partB);
        }
    }
    float al, ah, bl, bh;
    unpack2(partA, al, ah); float psA = al + ah;
    unpack2(partB, bl, bh); float psB = bl + bh;
#pragma unroll
    for (int s = 16; s; s >>= 1) {
        psA += __shfl_xor_sync(FULLM, psA, s);
        psB += __shfl_xor_sync(FULLM, psB, s);
    }
    hA = psA; hB = psB;
}

// ---------------------------------------------------------------------------
// Main kernel: 2 batch elements per warp, 4 warps/block.
// ---------------------------------------------------------------------------
__global__ __launch_bounds__(128, 3) void lstm_kernel(
    const float* __restrict__ x,
    const float* __restrict__ b2,
    float* __restrict__ out)
{
    __shared__ float sbuf[4][2 * TLEN + 8];   // interleaved (hA,hB) per t
    __shared__ u64 s_wh[2][4][4][32];         // both layers' Whh (8 KB)

    int tid = threadIdx.x;
    int warp = tid >> 5;
    int lane = tid & 31;
    int b0 = blockIdx.x * 8 + warp * 2;
    const float* xbA = x + (size_t)b0 * TLEN;
    const float* xbB = xbA + TLEN;

    // cooperative copy of Whh into smem
    {
        const u64* src = reinterpret_cast<const u64*>(&g_wh2[0][0][0][0]);
        u64* dst = &s_wh[0][0][0][0];
        for (int i = tid; i < 2 * 4 * 4 * 32; i += 128) dst[i] = src[i];
    }
    __syncthreads();

    u64 B[NPOLY];
#pragma unroll
    for (int m = 0; m < NPOLY; m++) {
        float cm = g_poly[m];
        B[m] = pack2(cm, cm);
    }

    u64 wx[4][4], wb[4][4], wr[4];
    float cA[8], cB[8];

    // ---------------- pass 1: layer 0 ----------------
#pragma unroll
    for (int p = 0; p < 4; p++) {
#pragma unroll
        for (int gte = 0; gte < 4; gte++) {
            wx[p][gte] = ldp(&g_wx2[0][p][gte][lane]);
            wb[p][gte] = ldp(&g_wb2[0][p][gte][lane]);
        }
        wr[p] = ldp(&g_wr2[0][p][lane]);
        cA[2 * p] = 0.0f; cA[2 * p + 1] = 0.0f;
        cB[2 * p] = 0.0f; cB[2 * p + 1] = 0.0f;
    }
    uint32_t whaddr = smem_u32(&s_wh[0][0][0][lane]);
    float2* srow = reinterpret_cast<float2*>(&sbuf[warp][0]);
    float hA = 0.0f, hB = 0.0f;
    float xrA = 0.0f, xrB = 0.0f;
    for (int t = 0; t < TLEN; t++) {
        if ((t & 31) == 0) {
            int ti = t + lane;
            int tc = (ti < TLEN) ? ti : (TLEN - 1);
            xrA = xbA[tc];
            xrB = xbB[tc];
        }
        float xvA = __shfl_sync(FULLM, xrA, t & 31);
        float xvB = __shfl_sync(FULLM, xrB, t & 31);
        lstm_step2(xvA, xvB, hA, hB, wx, wb, wr, cA, cB, B, whaddr);
        if (lane == 0) srow[t] = make_float2(hA, hB);
    }
    __syncwarp();

    // ---------------- pass 2: layer 1 + fused head ----------------
#pragma unroll
    for (int p = 0; p < 4; p++) {
#pragma unroll
        for (int gte = 0; gte < 4; gte++) {
            wx[p][gte] = ldp(&g_wx2[1][p][gte][lane]);
            wb[p][gte] = ldp(&g_wb2[1][p][gte][lane]);
        }
        wr[p] = ldp(&g_wr2[1][p][lane]);
        cA[2 * p] = 0.0f; cA[2 * p + 1] = 0.0f;
        cB[2 * p] = 0.0f; cB[2 * p + 1] = 0.0f;
    }
    whaddr = smem_u32(&s_wh[1][0][0][lane]);
    hA = 0.0f; hB = 0.0f;
    float a0A = 0.0f, a1A = 0.0f, a2A = 0.0f, a3A = 0.0f;
    float a0B = 0.0f, a1B = 0.0f, a2B = 0.0f, a3B = 0.0f;
    for (int t = 0; t < TLEN; t++) {
        float2 hv = srow[t];
        lstm_step2(hv.x, hv.y, hA, hB, wx, wb, wr, cA, cB, B, whaddr);
        const float* wrow = g_w1t + t * 128;
        float w0 = wrow[lane], w1 = wrow[lane + 32];
        float w2 = wrow[lane + 64], w3 = wrow[lane + 96];
        a0A = fmaf(hA, w0, a0A); a0B = fmaf(hB, w0, a0B);
        a1A = fmaf(hA, w1, a1A); a1B = fmaf(hB, w1, a1B);
        a2A = fmaf(hA, w2, a2A); a2B = fmaf(hB, w2, a2B);
        a3A = fmaf(hA, w3, a3A); a3B = fmaf(hB, w3, a3B);
    }

    // head: out = relu(acc + b1) @ W2 + b2   (padding is zero -> no effect)
    float p0 = g_b1p[lane], p1 = g_b1p[lane + 32];
    float p2 = g_b1p[lane + 64], p3 = g_b1p[lane + 96];
    float q0 = g_w2p[lane], q1 = g_w2p[lane + 32];
    float q2 = g_w2p[lane + 64], q3 = g_w2p[lane + 96];
    float sA = fmaxf(a0A + p0, 0.0f) * q0 + fmaxf(a1A + p1, 0.0f) * q1
             + fmaxf(a2A + p2, 0.0f) * q2 + fmaxf(a3A + p3, 0.0f) * q3;
    float sB = fmaxf(a0B + p0, 0.0f) * q0 + fmaxf(a1B + p1, 0.0f) * q1
             + fmaxf(a2B + p2, 0.0f) * q2 + fmaxf(a3B + p3, 0.0f) * q3;
#pragma unroll
    for (int sf = 16; sf; sf >>= 1) {
        sA += __shfl_xor_sync(FULLM, sA, sf);
        sB += __shfl_xor_sync(FULLM, sB, sf);
    }
    if (lane == 0) {
        float bb = b2[0];
        out[b0]     = sA + bb;
        out[b0 + 1] = sB + bb;
    }
}

// ---------------------------------------------------------------------------
// kernel_launch
// ---------------------------------------------------------------------------
extern "C" void kernel_launch(void* const* d_in, const int* in_sizes, int n_in,
                              void* d_out, int out_size)
{
    const float* x    = (const float*)d_in[0];
    const float* Wih0 = (const float*)d_in[1];
    const float* Whh0 = (const float*)d_in[2];
    const float* bih0 = (const float*)d_in[3];
    const float* bhh0 = (const float*)d_in[4];
    const float* Whr0 = (const float*)d_in[5];
    const float* Wih1 = (const float*)d_in[6];
    const float* Whh1 = (const float*)d_in[7];
    const float* bih1 = (const float*)d_in[8];
    const float* bhh1 = (const float*)d_in[9];
    const float* Whr1 = (const float*)d_in[10];
    const float* W1   = (const float*)d_in[11];
    const float* b1   = (const float*)d_in[12];
    const float* W2   = (const float*)d_in[13];
    const float* b2   = (const float*)d_in[14];
    float* out = (float*)d_out;

    int B = in_sizes[0] / TLEN;   // 16384

    prep_kernel<<<TLEN + 1, 128>>>(Wih0, Whh0, bih0, bhh0, Whr0,
                                   Wih1, Whh1, bih1, bhh1, Whr1,
                                   W1, b1, W2);
    lstm_kernel<<<B / 8, 128>>>(x, b2, out);
}